// round 16
// baseline (speedup 1.0000x reference)
#include <cuda_runtime.h>
#include <cuda_fp16.h>
#include <cstdint>

#define B_  4
#define H_  16
#define SQ  2048
#define DH  64
#define BM  128
#define BN  64
#define NITER (SQ / BN)     // 32
#define THREADS 256
#define STRD 72             // fp16 smem row stride (halves)
#define QSCALE 0.1803368801111137f   // 0.125 * log2(e)

// 512 MB device scratch: unnormalized exp(s) in fp16, layout [B*H*S, S]
__device__ __half e_scratch[(size_t)B_ * H_ * SQ * SQ];
// packed mask bits: [S][32] uint64, bit c of word w = mask[row][w*64+c]
__device__ uint64_t mbits_g[(size_t)SQ * 32];

// smem (halves): Qh[128*72] Kh[2][64*72] Vh[2][64*72]  (+rinv reuses Qh space)
#define SMEM_BYTES ((128*STRD + 4*64*STRD) * 2)   // 55296

__device__ __forceinline__ uint32_t smaddr(const void* p) {
    return (uint32_t)__cvta_generic_to_shared(p);
}
__device__ __forceinline__ float ex2f(float x) {
    float r;
    asm("ex2.approx.f32 %0,%1;" : "=f"(r) : "f"(x));
    return r;
}
__device__ __forceinline__ void ldmx4(uint32_t r[4], uint32_t addr) {
    asm volatile("ldmatrix.sync.aligned.m8n8.x4.shared.b16 {%0,%1,%2,%3},[%4];"
                 : "=r"(r[0]), "=r"(r[1]), "=r"(r[2]), "=r"(r[3]) : "r"(addr));
}
__device__ __forceinline__ void ldmx4t(uint32_t r[4], uint32_t addr) {
    asm volatile("ldmatrix.sync.aligned.m8n8.x4.trans.shared.b16 {%0,%1,%2,%3},[%4];"
                 : "=r"(r[0]), "=r"(r[1]), "=r"(r[2]), "=r"(r[3]) : "r"(addr));
}
__device__ __forceinline__ void mma16816(float c[4], uint32_t a0, uint32_t a1, uint32_t a2,
                                         uint32_t a3, uint32_t b0, uint32_t b1) {
    asm volatile("mma.sync.aligned.m16n8k16.row.col.f32.f16.f16.f32 "
                 "{%0,%1,%2,%3},{%4,%5,%6,%7},{%8,%9},{%0,%1,%2,%3};"
                 : "+f"(c[0]), "+f"(c[1]), "+f"(c[2]), "+f"(c[3])
                 : "r"(a0), "r"(a1), "r"(a2), "r"(a3), "r"(b0), "r"(b1));
}
__device__ __forceinline__ uint32_t packh2(float a, float b) {
    __half2 h = __floats2half2_rn(a, b);
    return *(uint32_t*)&h;
}
// convert fp32 float4 -> fp16, 8B store
__device__ __forceinline__ void conv_hi_sts(__half* Hi, int r, int c4, float4 x) {
    uint2 uh;
    uh.x = packh2(x.x, x.y);
    uh.y = packh2(x.z, x.w);
    *(uint2*)&Hi[r * STRD + c4] = uh;
}

// ==================== k0: pack mask into bits ====================
__global__ void __launch_bounds__(256)
pack_mask(const int* __restrict__ mask)
{
    const int warp = (blockIdx.x * 256 + threadIdx.x) >> 5;   // row 0..2047
    const int lane = threadIdx.x & 31;
    if (warp >= SQ) return;
    const int* mr = mask + (size_t)warp * SQ;
    #pragma unroll 4
    for (int w = 0; w < 32; w++) {
        int m0 = mr[w * 64 + lane];
        int m1 = mr[w * 64 + 32 + lane];
        uint32_t b0 = __ballot_sync(0xffffffffu, m0 != 0);
        uint32_t b1 = __ballot_sync(0xffffffffu, m1 != 0);
        if (lane == 0) mbits_g[(size_t)warp * 32 + w] = (uint64_t)b0 | ((uint64_t)b1 << 32);
    }
}

// ==================== k1: QK, exp, e-store, PV, O, fused p-normalize ====================
__global__ void __launch_bounds__(THREADS, 2)
attn_k1(const float* __restrict__ q, const float* __restrict__ k,
        const float* __restrict__ v, float* __restrict__ outp,
        float* __restrict__ pattn)
{
    extern __shared__ __half sm[];
    __half* Qh  = sm;
    __half* KhB = Qh + 128 * STRD;            // 2 x 64*STRD
    __half* VhB = KhB + 2 * 64 * STRD;        // 2 x 64*STRD
    float*  rinv_s = (float*)sm;              // reused after main loop

    const int tid  = threadIdx.x;
    const int lane = tid & 31;
    const int warp = tid >> 5;
    const int g    = lane >> 2;
    const int tq   = lane & 3;
    const int wrow = warp * 16;
    const int m0   = blockIdx.x * BM;
    const int bh   = blockIdx.y;

    const float* qb = q + (size_t)bh * SQ * DH;
    const float* kb = k + (size_t)bh * SQ * DH;
    const float* vb = v + (size_t)bh * SQ * DH;
    __half*      eb = e_scratch + (size_t)bh * SQ * SQ;
    float*       pb = pattn + (size_t)bh * SQ * SQ;

    // per-thread slice coords for 64x64 tile loads (4 float4 each)
    int tr[4], tc[4];
    #pragma unroll
    for (int i = 0; i < 4; i++) {
        int s = tid + i * THREADS;
        tr[i] = s >> 4;
        tc[i] = (s & 15) * 4;
    }

    // ---- prologue: load Q (pre-scaled by 0.125*log2e) ; K0,V0 -> buf 0 ----
    #pragma unroll
    for (int i = 0; i < 8; i++) {
        int s  = tid + i * THREADS;
        int r  = s >> 4;
        int c4 = (s & 15) * 4;
        float4 x = *(const float4*)(qb + (size_t)(m0 + r) * DH + c4);
        x.x *= QSCALE; x.y *= QSCALE; x.z *= QSCALE; x.w *= QSCALE;
        conv_hi_sts(Qh, r, c4, x);
    }
    {
        float4 kreg[4], vreg[4];
        #pragma unroll
        for (int i = 0; i < 4; i++) kreg[i] = *(const float4*)(kb + (size_t)tr[i] * DH + tc[i]);
        #pragma unroll
        for (int i = 0; i < 4; i++) vreg[i] = *(const float4*)(vb + (size_t)tr[i] * DH + tc[i]);
        #pragma unroll
        for (int i = 0; i < 4; i++) conv_hi_sts(KhB, tr[i], tc[i], kreg[i]);
        #pragma unroll
        for (int i = 0; i < 4; i++) conv_hi_sts(VhB, tr[i], tc[i], vreg[i]);
    }

    float oacc[8][4];
    #pragma unroll
    for (int j = 0; j < 8; j++) { oacc[j][0]=0.f; oacc[j][1]=0.f; oacc[j][2]=0.f; oacc[j][3]=0.f; }
    float rs0 = 0.f, rs1 = 0.f;
    const int prow0 = m0 + wrow + g;
    const int shb = 2 * tq;    // base bit shift within each 8-bit group

    for (int it = 0; it < NITER; it++) {
        const int n0  = it * BN;
        const int nn  = ((it + 1 < NITER) ? (it + 1) : 0) * BN;
        const int cur = it & 1;
        const int nxt = cur ^ 1;
        __half* Kh = KhB + cur * 64 * STRD;
        __half* Vh = VhB + cur * 64 * STRD;

        __syncthreads();   // single barrier: cur buffers written, nxt buffers free

        // ---- prefetch K(it+1) into registers (hidden under compute) ----
        float4 kreg[4];
        #pragma unroll
        for (int i = 0; i < 4; i++)
            kreg[i] = *(const float4*)(kb + (size_t)(nn + tr[i]) * DH + tc[i]);

        // ---- packed mask words for this thread's two rows ----
        uint64_t w0 = mbits_g[(size_t)prow0 * 32 + it];
        uint64_t w1 = mbits_g[(size_t)(prow0 + 8) * 32 + it];

        // ---- QK^T: S[16x64] per warp; single fp16 MMA (Q pre-scaled) ----
        float sacc[8][4];
        #pragma unroll
        for (int j = 0; j < 8; j++) { sacc[j][0]=0.f; sacc[j][1]=0.f; sacc[j][2]=0.f; sacc[j][3]=0.f; }

        #pragma unroll
        for (int kc = 0; kc < 4; kc++) {
            uint32_t aq[4];
            {
                int row = wrow + (lane & 15);
                int col = kc * 16 + ((lane & 16) ? 8 : 0);
                ldmx4(aq, smaddr(&Qh[row * STRD + col]));
            }
            #pragma unroll
            for (int jp = 0; jp < 4; jp++) {
                uint32_t bh4[4];
                int row = jp * 16 + (lane & 7) + ((lane & 16) ? 8 : 0);
                int col = kc * 16 + ((lane & 8) ? 8 : 0);
                ldmx4(bh4, smaddr(&Kh[row * STRD + col]));
                mma16816(sacc[2*jp],   aq[0],aq[1],aq[2],aq[3], bh4[0], bh4[1]);
                mma16816(sacc[2*jp+1], aq[0],aq[1],aq[2],aq[3], bh4[2], bh4[3]);
            }
        }

        // ---- prefetch V(it+1) into registers ----
        float4 vreg[4];
        #pragma unroll
        for (int i = 0; i < 4; i++)
            vreg[i] = *(const float4*)(vb + (size_t)(nn + tr[i]) * DH + tc[i]);

        // ---- mask bits, exp2, rowsum, e-store (fp16 scratch), pack P ----
        uint32_t pk[8][2];
        #pragma unroll
        for (int j = 0; j < 8; j++) {
            int col = n0 + j * 8 + shb;
            uint32_t b0 = (uint32_t)(w0 >> (8 * j + shb));
            uint32_t b1 = (uint32_t)(w1 >> (8 * j + shb));
            float e0 = (b0 & 1u) ? ex2f(sacc[j][0]) : 0.f;
            float e1 = (b0 & 2u) ? ex2f(sacc[j][1]) : 0.f;
            float e2 = (b1 & 1u) ? ex2f(sacc[j][2]) : 0.f;
            float e3 = (b1 & 2u) ? ex2f(sacc[j][3]) : 0.f;
            rs0 += e0 + e1;
            rs1 += e2 + e3;
            uint32_t p01 = packh2(e0, e1);
            uint32_t p23 = packh2(e2, e3);
            *(uint32_t*)(eb + (size_t)prow0 * SQ + col)       = p01;
            *(uint32_t*)(eb + (size_t)(prow0 + 8) * SQ + col) = p23;
            pk[j][0] = p01;
            pk[j][1] = p23;
        }

        // ---- convert K(it+1) regs -> nxt buffer (kreg dies here) ----
        #pragma unroll
        for (int i = 0; i < 4; i++)
            conv_hi_sts(KhB + nxt * 64 * STRD, tr[i], tc[i], kreg[i]);

        // ---- O += P @ V ----
        #pragma unroll
        for (int kcp = 0; kcp < 4; kcp++) {
            uint32_t a0 = pk[2*kcp][0], a1 = pk[2*kcp][1];
            uint32_t a2 = pk[2*kcp+1][0], a3 = pk[2*kcp+1][1];
            #pragma unroll
            for (int jdp = 0; jdp < 4; jdp++) {
                uint32_t bv[4];
                int row = kcp * 16 + (lane & 7) + ((lane & 8) ? 8 : 0);
                int col = jdp * 16 + ((lane & 16) ? 8 : 0);
                ldmx4t(bv, smaddr(&Vh[row * STRD + col]));
                mma16816(oacc[2*jdp],   a0,a1,a2,a3, bv[0], bv[1]);
                mma16816(oacc[2*jdp+1], a0,a1,a2,a3, bv[2], bv[3]);
            }
        }

        // ---- convert V(it+1) regs -> nxt buffer ----
        #pragma unroll
        for (int i = 0; i < 4; i++)
            conv_hi_sts(VhB + nxt * 64 * STRD, tr[i], tc[i], vreg[i]);
    }

    // ---- rowsum reduce within quad; write normalized O ----
    rs0 += __shfl_xor_sync(0xffffffffu, rs0, 1);
    rs0 += __shfl_xor_sync(0xffffffffu, rs0, 2);
    rs1 += __shfl_xor_sync(0xffffffffu, rs1, 1);
    rs1 += __shfl_xor_sync(0xffffffffu, rs1, 2);
    float ri0 = (rs0 > 0.f) ? (1.f / rs0) : 0.f;
    float ri1 = (rs1 > 0.f) ? (1.f / rs1) : 0.f;

    #pragma unroll
    for (int jd = 0; jd < 8; jd++) {
        int col = jd * 8 + 2 * tq;
        float2 o0; o0.x = oacc[jd][0] * ri0; o0.y = oacc[jd][1] * ri0;
        float2 o1; o1.x = oacc[jd][2] * ri1; o1.y = oacc[jd][3] * ri1;
        *(float2*)(outp + ((size_t)bh * SQ + prow0) * DH + col)     = o0;
        *(float2*)(outp + ((size_t)bh * SQ + prow0 + 8) * DH + col) = o1;
    }

    // ---- fused tail: normalize this CTA's p band [128 x 2048] ----
    __syncthreads();                       // everyone done reading Qh/Kh/Vh
    if (tq == 0) {
        rinv_s[wrow + g]     = ri0;
        rinv_s[wrow + 8 + g] = ri1;
    }
    __syncthreads();

    // warp handles its own 16 rows; per row: 8x LDG.128 (fp16) -> 16x STG.128 (fp32)
    for (int rr = 0; rr < 16; rr++) {
        const int r = wrow + rr;
        const float ri = rinv_s[r];
        const __half* er = eb + (size_t)(m0 + r) * SQ;
        float*        pr = pb + (size_t)(m0 + r) * SQ;
        #pragma unroll
        for (int c = 0; c < 8; c++) {
            uint4 d = *(const uint4*)(er + c * 256 + lane * 8);
            float2 f0 = __half22float2(*(__half2*)&d.x);
            float2 f1 = __half22float2(*(__half2*)&d.y);
            float2 f2 = __half22float2(*(__half2*)&d.z);
            float2 f3 = __half22float2(*(__half2*)&d.w);
            float4 o0 = make_float4(f0.x * ri, f0.y * ri, f1.x * ri, f1.y * ri);
            float4 o1 = make_float4(f2.x * ri, f2.y * ri, f3.x * ri, f3.y * ri);
            *(float4*)(pr + c * 256 + lane * 8)     = o0;
            *(float4*)(pr + c * 256 + lane * 8 + 4) = o1;
        }
    }
}

extern "C" void kernel_launch(void* const* d_in, const int* in_sizes, int n_in,
                              void* d_out, int out_size)
{
    const float* q    = (const float*)d_in[0];
    const float* k    = (const float*)d_in[1];
    const float* v    = (const float*)d_in[2];
    const int*   mask = (const int*)d_in[3];

    float* outp  = (float*)d_out;                                   // [B,H,S,D]
    float* pattn = (float*)d_out + (size_t)B_ * H_ * SQ * DH;       // [B,H,S,S]

    cudaFuncSetAttribute(attn_k1, cudaFuncAttributeMaxDynamicSharedMemorySize, SMEM_BYTES);

    pack_mask<<<SQ * 32 / 256, 256>>>(mask);

    dim3 grid1(SQ / BM, B_ * H_);
    attn_k1<<<grid1, THREADS, SMEM_BYTES>>>(q, k, v, outp, pattn);
}